// round 12
// baseline (speedup 1.0000x reference)
#include <cuda_runtime.h>
#include <cuda_fp16.h>
#include <math.h>
#include <stdint.h>

#define N_SEQ 2048
#define EMB   1024
#define KVE   256
#define HD    64
#define QH    16

// ---------------- scratch (device globals; no allocation) ----------------
__device__ uint32_t dWpq[16 * 32 * 1024];  // weights pre-packed PB blocks
__device__ uint32_t dWpk[4 * 32 * 1024];
__device__ uint32_t dWpv[4 * 32 * 1024];
__device__ uint32_t dQh[N_SEQ * 512];      // q proj out, fp16 rows (log2e folded)
__device__ uint32_t dKpg[4 * 32 * 2048];   // packed K per (kvh, s-chunk)
__device__ uint32_t dVpg[4 * 32 * 2048];   // packed V per (kvh, s-chunk)
__device__ float    g_attn[N_SEQ * EMB];

// ---------------- helpers ----------------
__device__ __forceinline__ uint32_t h2(float lo, float hi) {
    __half2 h = __floats2half2_rn(lo, hi);
    return *reinterpret_cast<uint32_t*>(&h);
}
__device__ __forceinline__ float ex2(float x) {
    float y;
    asm("ex2.approx.ftz.f32 %0, %1;" : "=f"(y) : "f"(x));
    return y;
}
__device__ __forceinline__ void mma_f16(float* d,
    uint32_t a0, uint32_t a1, uint32_t a2, uint32_t a3,
    uint32_t b0, uint32_t b1)
{
    asm volatile(
        "mma.sync.aligned.m16n8k16.row.col.f32.f16.f16.f32 "
        "{%0,%1,%2,%3}, {%4,%5,%6,%7}, {%8,%9}, {%0,%1,%2,%3};\n"
        : "+f"(d[0]), "+f"(d[1]), "+f"(d[2]), "+f"(d[3])
        : "r"(a0), "r"(a1), "r"(a2), "r"(a3), "r"(b0), "r"(b1));
}
__device__ __forceinline__ void cp16(uint32_t daddr, const void* src) {
    asm volatile("cp.async.cg.shared.global [%0], [%1], 16;\n"
                 :: "r"(daddr), "l"(src));
}
__device__ __forceinline__ void cp_commit() {
    asm volatile("cp.async.commit_group;\n");
}
template<int N>
__device__ __forceinline__ void cp_wait() {
    asm volatile("cp.async.wait_group %0;\n" :: "n"(N));
}

// =========================================================================
// prep: weights only -> packed PB-block fp16 layout.
// Global [b64][kk32][kc16][nt8][64].
// =========================================================================
__device__ __forceinline__ void pack_w(const float* __restrict__ W,
                                       uint32_t* __restrict__ D, int d) {
    int b = d >> 15, rem = d & 32767;
    int kk = rem >> 10, rem2 = rem & 1023;
    int kc = rem2 >> 9, t9 = rem2 & 511;
    int nt = t9 >> 6, pos = t9 & 63;
    int slot = pos & 1, qq = pos >> 1;
    int r7 = qq >> 2, tq = qq & 3;
    int m = b * 64 + nt * 8 + r7;
    int k = kk * 32 + kc * 16 + slot * 8 + tq * 2;
    D[d] = h2(W[m * 1024 + k], W[m * 1024 + k + 1]);
}

__global__ __launch_bounds__(256) void prep_kernel(
    const float* __restrict__ wq, const float* __restrict__ wk,
    const float* __restrict__ wv)
{
    int base = blockIdx.x * 1024 + threadIdx.x;
#pragma unroll
    for (int i = 0; i < 4; i++) {
        int idx = base + i * 256;
        if (idx < 524288)       pack_w(wq, dWpq, idx);
        else if (idx < 655360)  pack_w(wk, dWpk, idx - 524288);
        else                    pack_w(wv, dWpv, idx - 655360);
    }
}

// =========================================================================
// proj v4: BM=128 x BN=128, BK=64, 16 iters, 2-stage cp.async ring.
// X raw fp32, stride-72 rows (72 % 32 == 8 -> conflict-free LDS.64).
// stage = X 9216 + W 4096 u32 = 53248 B; 2 stages = 106496 B. 2 CTAs/SM.
// =========================================================================
#define PJ_STG 13312

__global__ __launch_bounds__(256, 2) void proj_tc2(
    const float* __restrict__ xq, const float* __restrict__ xk,
    const float* __restrict__ xv,
    const float* __restrict__ bq, const float* __restrict__ bk,
    const float* __restrict__ bv)
{
    extern __shared__ uint32_t sh[];
    const int tid  = threadIdx.x;
    const int lane = tid & 31;
    const int w    = tid >> 5;
    const int g    = lane >> 2;
    const int t    = lane & 3;
    const int wm   = w * 16;
    const int lane2 = lane * 2;

    const float* Xa;
    const uint32_t* Wa;
    const float* Bp;
    int n0, m0, mode;
    {
        int bid = blockIdx.x;
        if (bid < 128) {
            Xa = xq; Wa = dWpq; Bp = bq; mode = 0;
            m0 = (bid & 7) * 128; n0 = (bid >> 3) * 128;
        } else if (bid < 160) {
            int l = bid - 128;
            Xa = xk; Wa = dWpk; Bp = bk; mode = 1;
            m0 = (l & 1) * 128; n0 = (l >> 1) * 128;
        } else {
            int l = bid - 160;
            Xa = xv; Wa = dWpv; Bp = bv; mode = 2;
            m0 = (l & 1) * 128; n0 = (l >> 1) * 128;
        }
    }
    const uint32_t sb = (uint32_t)__cvta_generic_to_shared(sh);

    auto issue = [&](int stage, int kk64) {
        uint32_t d0 = sb + stage * (PJ_STG * 4);
#pragma unroll
        for (int i = 0; i < 8; i++) {            // X fp32: 2048 granules
            int gg = tid + i * 256;
            int r = gg >> 4, ch = gg & 15;
            cp16(d0 + r * 288 + ch * 16,
                 Xa + (size_t)(n0 + r) * 1024 + kk64 * 64 + ch * 4);
        }
        uint32_t wd = d0 + 9216 * 4;
#pragma unroll
        for (int i = 0; i < 4; i++) {            // W: 1024 granules
            int gg = tid + i * 256;
            int h = gg >> 9, rem = gg & 511;
            int kcp = rem >> 8, t8 = rem & 255, nt = t8 >> 4, p4 = t8 & 15;
            int b64 = (m0 >> 6) + (nt >> 3);
            cp16(wd + gg * 16,
                 Wa + ((size_t)b64 * 32 + kk64 * 2 + h) * 1024 + kcp * 512 +
                     (nt & 7) * 64 + p4 * 4);
        }
    };

    float acc[16][4];
#pragma unroll
    for (int nt = 0; nt < 16; nt++)
#pragma unroll
        for (int i = 0; i < 4; i++) acc[nt][i] = 0.f;

    issue(0, 0); cp_commit();

    for (int kk = 0; kk < 16; kk++) {
        cp_wait<0>();
        __syncthreads();
        if (kk < 15) { issue((kk + 1) & 1, kk + 1); cp_commit(); }

        const uint32_t* stgu = sh + (kk & 1) * PJ_STG;
        const float* Xs = (const float*)stgu;
        const uint32_t* Ws = stgu + 9216;
#pragma unroll
        for (int kc = 0; kc < 4; kc++) {
            const float* ap = Xs + (wm + g) * 72 + kc * 16 + 2 * t;
            float2 lo0 = *(const float2*)(ap);
            float2 lo1 = *(const float2*)(ap + 8 * 72);
            float2 hi0 = *(const float2*)(ap + 8);
            float2 hi1 = *(const float2*)(ap + 8 * 72 + 8);
            uint32_t a0 = h2(lo0.x, lo0.y);
            uint32_t a1 = h2(lo1.x, lo1.y);
            uint32_t a2 = h2(hi0.x, hi0.y);
            uint32_t a3 = h2(hi1.x, hi1.y);
            const uint32_t* Wb = Ws + (kc >> 1) * 2048 + (kc & 1) * 1024;
#pragma unroll
            for (int nt = 0; nt < 16; nt++) {
                uint2 b = *(const uint2*)(Wb + nt * 64 + lane2);
                mma_f16(acc[nt], a0, a1, a2, a3, b.x, b.y);
            }
        }
    }

    const int rA = n0 + wm + g, rB = rA + 8;
    if (mode == 0) {
        const float QS = 0.125f * 1.4426950408889634f;   // fold log2e
#pragma unroll
        for (int nt = 0; nt < 16; nt++) {
            int col = m0 + nt * 8 + 2 * t;
            float b0 = Bp[col], b1 = Bp[col + 1];
            dQh[(size_t)rA * 512 + (col >> 1)] =
                h2((acc[nt][0] + b0) * QS, (acc[nt][1] + b1) * QS);
            dQh[(size_t)rB * 512 + (col >> 1)] =
                h2((acc[nt][2] + b0) * QS, (acc[nt][3] + b1) * QS);
        }
    } else if (mode == 1) {
#pragma unroll
        for (int nt = 0; nt < 16; nt++) {
            int col = m0 + nt * 8 + 2 * t;
            int kvh = col >> 6, d = col & 63;
            float b0 = Bp[col], b1 = Bp[col + 1];
            uint32_t ia = ((uint32_t)((kvh * 32 + (rA >> 6)) * 4 + (d >> 4))) * 512
                        + ((rA & 63) >> 3) * 64 + ((rA & 7) * 4 + t) * 2
                        + ((d & 15) >> 3);
            uint32_t ib = ((uint32_t)((kvh * 32 + (rB >> 6)) * 4 + (d >> 4))) * 512
                        + ((rB & 63) >> 3) * 64 + ((rB & 7) * 4 + t) * 2
                        + ((d & 15) >> 3);
            dKpg[ia] = h2(acc[nt][0] + b0, acc[nt][1] + b1);
            dKpg[ib] = h2(acc[nt][2] + b0, acc[nt][3] + b1);
        }
    } else {
#pragma unroll
        for (int nt = 0; nt < 16; nt++) {
            int col = m0 + nt * 8 + 2 * t;
            int kvh = col >> 6, d = col & 63;
            float b0 = Bp[col], b1 = Bp[col + 1];
            float a0 = acc[nt][0] + b0, a1 = acc[nt][1] + b1;
            float a2 = acc[nt][2] + b0, a3 = acc[nt][3] + b1;
            float o0 = __shfl_xor_sync(0xffffffffu, a0, 4);
            float o1 = __shfl_xor_sync(0xffffffffu, a1, 4);
            float o2 = __shfl_xor_sync(0xffffffffu, a2, 4);
            float o3 = __shfl_xor_sync(0xffffffffu, a3, 4);
            if ((g & 1) == 0) {
#define VIDX(s, dd) (((uint32_t)((kvh * 32 + ((s) >> 6)) * 4 + (((s) & 63) >> 4))) * 512 \
                     + (((dd) >> 3) * 64) + ((((dd) & 7) * 4 + (((s) >> 1) & 3)) * 2) \
                     + ((((s) >> 3) & 1)))
                dVpg[VIDX(rA, d)]     = h2(a0, o0);
                dVpg[VIDX(rA, d + 1)] = h2(a1, o1);
                dVpg[VIDX(rB, d)]     = h2(a2, o2);
                dVpg[VIDX(rB, d + 1)] = h2(a3, o3);
#undef VIDX
            }
        }
    }
}

// =========================================================================
// attn v5: BN=128 per stage, 16 outer iters, 2-stage ring; two 64-col
// halves computed sequentially (registers stay at known-good level).
// Softmax: P = 2^S (log2e folded in q), row sums via ones-B MMAs.
// smem = Q 4608 + 2*8192 u32 = 83968 B. 2 CTAs/SM.
// =========================================================================
#define BM 128
#define A_ST 8192          // u32 per stage: K 4096 + V 4096

__global__ __launch_bounds__(256, 2) void attn_kernel()
{
    extern __shared__ uint32_t smu[];
    uint32_t* Qs = smu;                       // [128][36]

    const int tid  = threadIdx.x;
    const int lane = tid & 31;
    const int w    = tid >> 5;
    const int g    = lane >> 2;
    const int t    = lane & 3;
    const int wm   = w * 16;
    const int head = blockIdx.y;
    const int kvh  = head >> 2;
    const int m0   = blockIdx.x * BM;
    const int lane2 = lane * 2;
    const uint32_t sb = (uint32_t)__cvta_generic_to_shared(smu);
    const uint32_t ONE2 = 0x3C003C00u;        // half2(1,1)

    auto issue_kv = [&](int st, int p) {      // p = s-chunk pair 0..15
        const uint32_t* Ksrc = dKpg + (((size_t)kvh * 16 + p) << 12);
        const uint32_t* Vsrc = dVpg + (((size_t)kvh * 16 + p) << 12);
        uint32_t kd = sb + (4608 + st * A_ST) * 4;
        uint32_t vd = kd + 4096 * 4;
#pragma unroll
        for (int i = 0; i < 4; i++) {
            int gg = tid + i * 256;
            cp16(kd + gg * 16, Ksrc + gg * 4);
            cp16(vd + gg * 16, Vsrc + gg * 4);
        }
    };

    // Q: fp16 rows (head slice), stride 36 u32 (=144 B).
#pragma unroll
    for (int i = 0; i < 4; i++) {
        int gg = tid + i * 256;
        int row = gg >> 3, ch = gg & 7;
        cp16(sb + row * 144 + ch * 16,
             dQh + (size_t)(m0 + row) * 512 + head * 32 + ch * 4);
    }
    issue_kv(0, 0);
    cp_commit();
    cp_wait<0>();
    __syncthreads();

    uint32_t qf[4][4];
#pragma unroll
    for (int kc = 0; kc < 4; kc++) {
        const uint32_t* src = Qs + (wm + g) * 36 + kc * 8 + t;
        qf[kc][0] = src[0];
        qf[kc][1] = src[8 * 36];
        qf[kc][2] = src[4];
        qf[kc][3] = src[8 * 36 + 4];
    }

    float of[8][4];
#pragma unroll
    for (int nt = 0; nt < 8; nt++)
#pragma unroll
        for (int i = 0; i < 4; i++) of[nt][i] = 0.f;
    float os[4] = {0.f, 0.f, 0.f, 0.f};       // ones-MMA row sums

    for (int ci = 0; ci < 16; ci++) {
        if (ci > 0) { cp_wait<0>(); __syncthreads(); }
        if (ci < 15) { issue_kv((ci + 1) & 1, ci + 1); cp_commit(); }

        const uint32_t* stg = smu + 4608 + (ci & 1) * A_ST;

#pragma unroll
        for (int j = 0; j < 2; j++) {
            const uint32_t* Kb = stg + j * 2048;
            const uint32_t* Vb = stg + 4096 + j * 2048;

            // ---- S = Q @ K^T (log2-domain logits) ----
            float sf[8][4];
#pragma unroll
            for (int nt = 0; nt < 8; nt++)
#pragma unroll
                for (int i = 0; i < 4; i++) sf[nt][i] = 0.f;
#pragma unroll
            for (int kc = 0; kc < 4; kc++)
#pragma unroll
                for (int nt = 0; nt < 8; nt++) {
                    uint2 b = *(const uint2*)(Kb + kc * 512 + nt * 64 + lane2);
                    mma_f16(sf[nt], qf[kc][0], qf[kc][1], qf[kc][2], qf[kc][3],
                            b.x, b.y);
                }

            // ---- P = 2^S ----
#pragma unroll
            for (int nt = 0; nt < 8; nt++) {
                sf[nt][0] = ex2(sf[nt][0]);
                sf[nt][1] = ex2(sf[nt][1]);
                sf[nt][2] = ex2(sf[nt][2]);
                sf[nt][3] = ex2(sf[nt][3]);
            }

            // ---- S C-frags -> PV A-frags ----
            uint32_t pf[4][4];
#pragma unroll
            for (int kc = 0; kc < 4; kc++) {
                pf[kc][0] = h2(sf[2 * kc][0],     sf[2 * kc][1]);
                pf[kc][1] = h2(sf[2 * kc][2],     sf[2 * kc][3]);
                pf[kc][2] = h2(sf[2 * kc + 1][0], sf[2 * kc + 1][1]);
                pf[kc][3] = h2(sf[2 * kc + 1][2], sf[2 * kc + 1][3]);
            }

            // ---- O += P @ V ; row sums += P @ ones ----
#pragma unroll
            for (int kc = 0; kc < 4; kc++) {
#pragma unroll
                for (int nt = 0; nt < 8; nt++) {
                    uint2 b = *(const uint2*)(Vb + kc * 512 + nt * 64 + lane2);
                    mma_f16(of[nt], pf[kc][0], pf[kc][1], pf[kc][2], pf[kc][3],
                            b.x, b.y);
                }
                mma_f16(os, pf[kc][0], pf[kc][1], pf[kc][2], pf[kc][3],
                        ONE2, ONE2);
            }
        }
    }

    // ---- epilogue ----
    float rA = 1.f / os[0], rB = 1.f / os[2];
    const int rowA = m0 + wm + g;
    const int rowB = rowA + 8;
#pragma unroll
    for (int nt = 0; nt < 8; nt++) {
        int col = head * HD + nt * 8 + 2 * t;
        *(float2*)(g_attn + (size_t)rowA * EMB + col) =
            make_float2(of[nt][0] * rA, of[nt][1] * rA);
        *(float2*)(g_attn + (size_t)rowB * EMB + col) =
            make_float2(of[nt][2] * rB, of[nt][3] * rB);
    }
}

// =========================================================================
// LayerNorm v2: one WARP per row, 8 rows per 256-thread block, grid 256.
// Each lane: 8 independent float4 loads (MLP=8), pure shfl reduction,
// zero block barriers.
// =========================================================================
__global__ __launch_bounds__(256) void ln_kernel(
    const float* __restrict__ x, const float* __restrict__ gamma,
    const float* __restrict__ beta, float* __restrict__ out)
{
    const int lane = threadIdx.x & 31;
    const int wrp  = threadIdx.x >> 5;
    const int row  = blockIdx.x * 8 + wrp;

    const float4* xr = (const float4*)(x + (size_t)row * EMB);
    float4 v[8];
#pragma unroll
    for (int j = 0; j < 8; j++) v[j] = xr[lane + j * 32];

    float s = 0.f, ss = 0.f;
#pragma unroll
    for (int j = 0; j < 8; j++) {
        s  += v[j].x + v[j].y + v[j].z + v[j].w;
        ss += v[j].x * v[j].x + v[j].y * v[j].y +
              v[j].z * v[j].z + v[j].w * v[j].w;
    }
#pragma unroll
    for (int off = 16; off; off >>= 1) {
        s  += __shfl_xor_sync(0xffffffffu, s, off);
        ss += __shfl_xor_sync(0xffffffffu, ss, off);
    }

    const float mu   = s * (1.f / 1024.f);
    const float var  = ss * (1.f / 1024.f) - mu * mu;
    const float rstd = rsqrtf(var + 1e-5f);

    float4* orow = (float4*)(out + (size_t)row * EMB);
#pragma unroll
    for (int j = 0; j < 8; j++) {
        float4 gm = ((const float4*)gamma)[lane + j * 32];
        float4 bb = ((const float4*)beta)[lane + j * 32];
        float4 o;
        o.x = (v[j].x - mu) * rstd * gm.x + bb.x;
        o.y = (v[j].y - mu) * rstd * gm.y + bb.y;
        o.z = (v[j].z - mu) * rstd * gm.z + bb.z;
        o.w = (v[j].w - mu) * rstd * gm.w + bb.w;
        orow[lane + j * 32] = o;
    }
}

// =========================================================================
extern "C" void kernel_launch(void* const* d_in, const int* in_sizes, int n_in,
                              void* d_out, int out_size)
{
    const float* query = (const float*)d_in[0];
    const float* key   = (const float*)d_in[1];
    const float* value = (const float*)d_in[2];
    const float* Wq    = (const float*)d_in[3];
    const float* bq    = (const float*)d_in[4];
    const float* Wk    = (const float*)d_in[5];
    const float* bk    = (const float*)d_in[6];
    const float* Wv    = (const float*)d_in[7];
    const float* bv    = (const float*)d_in[8];
    const float* gamma = (const float*)d_in[9];
    const float* beta  = (const float*)d_in[10];
    float* out = (float*)d_out;

    float* attn;
    cudaGetSymbolAddress((void**)&attn, g_attn);

    const int PROJ_SMEM = 2 * PJ_STG * 4;                 // 106496
    const int ATTN_SMEM = (4608 + 2 * A_ST) * 4;          // 83968
    cudaFuncSetAttribute(proj_tc2,
                         cudaFuncAttributeMaxDynamicSharedMemorySize, PROJ_SMEM);
    cudaFuncSetAttribute(attn_kernel,
                         cudaFuncAttributeMaxDynamicSharedMemorySize, ATTN_SMEM);

    prep_kernel<<<768, 256>>>(Wq, Wk, Wv);
    proj_tc2<<<192, 256, PROJ_SMEM>>>(query, key, value, bq, bk, bv);
    attn_kernel<<<dim3(N_SEQ / BM, QH), 256, ATTN_SMEM>>>();
    ln_kernel<<<256, 256>>>(attn, gamma, beta, out);
}